// round 14
// baseline (speedup 1.0000x reference)
#include <cuda_runtime.h>
#include <cuda_bf16.h>
#include <cstdint>

#define BATCH 1024
#define INF   512
#define OUTF  512
#define BT    64
#define OT    64
#define KT    16
#define NSTAGES   (INF / KT)     // 32
#define MAIN_S    28             // stages done by main CTAs
#define NTILES    128            // 16 b-tiles x 8 o-tiles
#define NMAIN     128
#define NEXTRA    20             // 148 - 128
#define GRID_MAIN 148

typedef unsigned long long ull;

__device__ __forceinline__ float ex2f(float q) {
    float r; asm("ex2.approx.ftz.f32 %0, %1;" : "=f"(r) : "f"(q)); return r;
}

// Scratch (static __device__ globals: allocation-free per harness rules)
// Param per (o,i): float4 {inv = K/s, ty = -K*t/s, wzC = -2ln2*wz, nwz = -wz}:
// w = x*inv+ty -> ex2(-w^2) = exp(-u^2/2); wz*(u^2-1) = fma(-w^2, wzC, nwz)
__device__ float4 g_P[OUTF * INF];
__device__ float  g_Xx[INF * BATCH];      // x transposed [i][b]
__device__ float  g_wav[BATCH * OUTF];    // wavelet sums, stages 0..27
__device__ float  g_part[BATCH * OUTF];   // wavelet partials, stages 28..31
// bf16 2-way split of silu(x) [b][i] and base_weight [o][i] for HMMA GEMM
__device__ __nv_bfloat16 g_Ah[BATCH * INF], g_Al[BATCH * INF];
__device__ __nv_bfloat16 g_Wh[OUTF * INF], g_Wl[OUTF * INF];

#define PBLOCKS 1024   // OUTF*INF/256
#define TBLOCKS 512    // (INF/32) * (BATCH/32) transpose tiles

// ---------------------------------------------------------------------------
// Fused prep: blocks [0,PBLOCKS) pack params + split base_weight to bf16 hi/lo;
// blocks [PBLOCKS,+TBLOCKS): transpose x, compute silu, split to bf16 hi/lo.
// ---------------------------------------------------------------------------
__global__ void prep_all(const float* __restrict__ x,
                         const float* __restrict__ bw, const float* __restrict__ ww,
                         const float* __restrict__ sc, const float* __restrict__ tr) {
    if (blockIdx.x < PBLOCKS) {
        int idx = blockIdx.x * 256 + threadIdx.x;
        const float K = 0.84936056542f;          // sqrt(1/(2ln2))
        float inv = K * __frcp_rn(sc[idx]);
        float wz  = ww[idx];
        float4 p;
        p.x = inv;
        p.y = -tr[idx] * inv;
        p.z = -1.38629436112f * wz;              // -2ln2 * wz
        p.w = -wz;
        g_P[idx] = p;
        float wv = bw[idx];
        __nv_bfloat16 h = __float2bfloat16(wv);
        g_Wh[idx] = h;
        g_Wl[idx] = __float2bfloat16(wv - __bfloat162float(h));
    } else {
        __shared__ float tX[32][33];
        int bt = blockIdx.x - PBLOCKS;           // 0..511
        int i0 = (bt & 15) * 32;                 // 16 i-tiles
        int b0 = (bt >> 4) * 32;                 // 32 b-tiles
        int tc = threadIdx.x & 31;
        int tr_ = threadIdx.x >> 5;              // 0..7
        #pragma unroll
        for (int j = 0; j < 4; ++j) {
            int r = tr_ + 8 * j;                 // b offset on read
            float v = x[(size_t)(b0 + r) * INF + i0 + tc];
            float e = __expf(-v);
            float s = v / (1.0f + e);            // silu
            tX[r][tc] = v;
            __nv_bfloat16 h = __float2bfloat16(s);
            size_t ai = (size_t)(b0 + r) * INF + i0 + tc;
            g_Ah[ai] = h;
            g_Al[ai] = __float2bfloat16(s - __bfloat162float(h));
        }
        __syncthreads();
        #pragma unroll
        for (int j = 0; j < 4; ++j) {
            int r = tr_ + 8 * j;                 // i offset on write
            g_Xx[(size_t)(i0 + r) * BATCH + b0 + tc] = tX[tc][r];
        }
    }
}

// ---------------------------------------------------------------------------
// Wavelet kernel shared tiles (40 KB static)
// ---------------------------------------------------------------------------
__shared__ float4 sP[2][KT][OT];        // 32 KB (swizzled cols)
__shared__ float4 sX[2][KT][BT / 4];    //  8 KB

__device__ __forceinline__ void load_stage(int s, int buf, int b0, int o0, int tid) {
    const int k0 = s * KT;
    #pragma unroll
    for (int j = 0; j < 4; ++j) {
        int idx = j * 256 + tid;
        int k   = idx & 15;
        int o   = idx >> 4;
        const float4* src = &g_P[(size_t)(o0 + o) * INF + (k0 + k)];
        uint32_t dst = (uint32_t)__cvta_generic_to_shared(&sP[buf][k][o ^ (k & 7)]);
        asm volatile("cp.async.cg.shared.global [%0], [%1], 16;\n" :: "r"(dst), "l"(src));
    }
    {
        int k  = tid >> 4;
        int b4 = tid & 15;
        const float* srcx = &g_Xx[(size_t)(k0 + k) * BATCH + b0 + b4 * 4];
        uint32_t dstx = (uint32_t)__cvta_generic_to_shared(&sX[buf][k][b4]);
        asm volatile("cp.async.cg.shared.global [%0], [%1], 16;\n" :: "r"(dstx), "l"(srcx));
    }
    asm volatile("cp.async.commit_group;\n" ::);
}

// Wavelet-only: stages [s_begin, s_end) of tile (b0,o0); writes g_wav or g_part.
__device__ __forceinline__ void run_tile(int b0, int o0, int s_begin, int s_end,
                                         float* __restrict__ dst) {
    const int tid = threadIdx.x;
    const int tb  = tid & 15;        // 16 batch groups (4 b each)
    const int to  = tid >> 4;        // 16 o groups (4 o each)

    float acc[4][4];
    #pragma unroll
    for (int i = 0; i < 4; ++i)
        #pragma unroll
        for (int j = 0; j < 4; ++j) acc[i][j] = 0.0f;

    load_stage(s_begin, 0, b0, o0, tid);
    load_stage(s_begin + 1, 1, b0, o0, tid);

    #pragma unroll 1
    for (int s = s_begin; s < s_end; ++s) {
        asm volatile("cp.async.wait_group 1;\n" ::);
        __syncthreads();
        const int buf = (s - s_begin) & 1;

        #pragma unroll 8
        for (int k = 0; k < KT; ++k) {
            float4 xa = sX[buf][k][tb];
            float xv[4] = {xa.x, xa.y, xa.z, xa.w};
            #pragma unroll
            for (int oo = 0; oo < 4; ++oo) {
                float4 p = sP[buf][k][(4 * to + oo) ^ (k & 7)];
                #pragma unroll
                for (int bb = 0; bb < 4; ++bb) {
                    float w  = fmaf(xv[bb], p.x, p.y);     // K*(x-t)/s
                    float qn = w * (-w);                   // -w^2 (free src neg)
                    float e  = ex2f(qn);                   // exp(-u^2/2)
                    float mp = fmaf(qn, p.z, p.w);         // wz*(u^2-1)
                    acc[bb][oo] = fmaf(mp, e, acc[bb][oo]);// wavelet only
                }
            }
        }
        __syncthreads();
        if (s + 2 < s_end) load_stage(s + 2, buf, b0, o0, tid);
        else               asm volatile("cp.async.commit_group;\n" ::);
    }

    #pragma unroll
    for (int bb = 0; bb < 4; ++bb) {
        int b = b0 + 4 * tb + bb;
        float4 r;
        r.x = acc[bb][0]; r.y = acc[bb][1]; r.z = acc[bb][2]; r.w = acc[bb][3];
        *reinterpret_cast<float4*>(dst + (size_t)b * OUTF + o0 + 4 * to) = r;
    }
}

__global__ void __launch_bounds__(256)
wkan_main() {
    const int c = blockIdx.x;
    if (c < NMAIN) {
        int b0 = (c & 15) * BT;
        int o0 = (c >> 4) * OT;
        run_tile(b0, o0, 0, MAIN_S, g_wav);
    } else {
        for (int t = c - NMAIN; t < NTILES; t += NEXTRA) {
            int b0 = (t & 15) * BT;
            int o0 = (t >> 4) * OT;
            run_tile(b0, o0, MAIN_S, NSTAGES, g_part);
            __syncthreads();   // smem reuse across tiles
        }
    }
}

// ---------------------------------------------------------------------------
// Base GEMM via warp-level HMMA (mma.sync m16n8k16 bf16, baseline PTX ISA —
// no sm_103a-only features). Split precision: hh + hl + lh, f32 accumulate.
// A [b][k] row-major = 'row' operand; W [o][k] row-major = K×N col-major = 'col'.
// Fragments loaded directly from global (4B-aligned pair loads, L2-resident).
// CTA: 8 warps, tile 128b x 64o; warp w owns b-rows [w*16, w*16+16).
// ---------------------------------------------------------------------------
__device__ __forceinline__ void mma_bf16(float* c, const uint32_t* a,
                                         uint32_t b0, uint32_t b1) {
    asm volatile(
        "mma.sync.aligned.m16n8k16.row.col.f32.bf16.bf16.f32 "
        "{%0,%1,%2,%3}, {%4,%5,%6,%7}, {%8,%9}, {%0,%1,%2,%3};"
        : "+f"(c[0]), "+f"(c[1]), "+f"(c[2]), "+f"(c[3])
        : "r"(a[0]), "r"(a[1]), "r"(a[2]), "r"(a[3]), "r"(b0), "r"(b1));
}
__device__ __forceinline__ uint32_t ldu32(const __nv_bfloat16* p) {
    return *reinterpret_cast<const uint32_t*>(p);
}

__global__ void __launch_bounds__(256)
gemm_hmma(const float* __restrict__ bias, float* __restrict__ out) {
    const int tid  = threadIdx.x;
    const int warp = tid >> 5;
    const int lane = tid & 31;
    const int g    = lane >> 2;      // group id 0..7
    const int t    = lane & 3;       // thread-in-group
    const int rb   = blockIdx.x * 128 + warp * 16;   // warp's b-row base
    const int o0   = blockIdx.y * 64;

    float acc[8][4];
    #pragma unroll
    for (int n = 0; n < 8; ++n)
        #pragma unroll
        for (int j = 0; j < 4; ++j) acc[n][j] = 0.0f;

    #pragma unroll 4
    for (int k = 0; k < INF; k += 16) {
        // A fragments (m16k16): a0:(g, k+2t) a1:(g+8,·) a2:(g, +8) a3:(g+8, +8)
        uint32_t ah[4], al[4];
        {
            size_t r0 = (size_t)(rb + g)     * INF + k + 2 * t;
            size_t r1 = (size_t)(rb + g + 8) * INF + k + 2 * t;
            ah[0] = ldu32(&g_Ah[r0]);     ah[1] = ldu32(&g_Ah[r1]);
            ah[2] = ldu32(&g_Ah[r0 + 8]); ah[3] = ldu32(&g_Ah[r1 + 8]);
            al[0] = ldu32(&g_Al[r0]);     al[1] = ldu32(&g_Al[r1]);
            al[2] = ldu32(&g_Al[r0 + 8]); al[3] = ldu32(&g_Al[r1 + 8]);
        }
        #pragma unroll
        for (int n = 0; n < 8; ++n) {
            // B fragments (k16n8): b0:(n=g, k+2t) b1:(n=g, k+2t+8)
            size_t wr = (size_t)(o0 + n * 8 + g) * INF + k + 2 * t;
            uint32_t bh0 = ldu32(&g_Wh[wr]), bh1 = ldu32(&g_Wh[wr + 8]);
            uint32_t bl0 = ldu32(&g_Wl[wr]), bl1 = ldu32(&g_Wl[wr + 8]);
            mma_bf16(acc[n], ah, bh0, bh1);   // hh
            mma_bf16(acc[n], ah, bl0, bl1);   // hl
            mma_bf16(acc[n], al, bh0, bh1);   // lh
        }
    }

    // Epilogue: D layout d0,d1:(row g, cols 2t,2t+1); d2,d3:(row g+8, same).
    // out = gemm + bias + g_wav + g_part, float2 stores.
    #pragma unroll
    for (int n = 0; n < 8; ++n) {
        int oc = o0 + n * 8 + 2 * t;
        float2 bv = *reinterpret_cast<const float2*>(&bias[oc]);
        #pragma unroll
        for (int half = 0; half < 2; ++half) {
            int b = rb + g + half * 8;
            size_t off = (size_t)b * OUTF + oc;
            float2 wv = *reinterpret_cast<const float2*>(&g_wav[off]);
            float2 pv = *reinterpret_cast<const float2*>(&g_part[off]);
            float2 r;
            r.x = acc[n][2 * half]     + bv.x + wv.x + pv.x;
            r.y = acc[n][2 * half + 1] + bv.y + wv.y + pv.y;
            *reinterpret_cast<float2*>(&out[off]) = r;
        }
    }
}

// ---------------------------------------------------------------------------
extern "C" void kernel_launch(void* const* d_in, const int* in_sizes, int n_in,
                              void* d_out, int out_size) {
    (void)in_sizes; (void)n_in; (void)out_size;
    const float* x    = (const float*)d_in[0];
    const float* bw   = (const float*)d_in[1];
    const float* ww   = (const float*)d_in[2];
    const float* sc   = (const float*)d_in[3];
    const float* tr   = (const float*)d_in[4];
    const float* bias = (const float*)d_in[5];
    float* out = (float*)d_out;

    prep_all<<<PBLOCKS + TBLOCKS, 256>>>(x, bw, ww, sc, tr);
    wkan_main<<<GRID_MAIN, 256>>>();
    gemm_hmma<<<dim3(8, 8), 256>>>(bias, out);
}

// round 15
// speedup vs baseline: 1.4297x; 1.4297x over previous
#include <cuda_runtime.h>
#include <cuda_bf16.h>
#include <cstdint>

#define BATCH 1024
#define INF   512
#define OUTF  512
#define BT    64
#define OT    64
#define KT    16
#define NSTAGES   (INF / KT)     // 32
#define MAIN_S    28             // stages done by main CTAs
#define NTILES    128            // 16 b-tiles x 8 o-tiles
#define NMAIN     128
#define NEXTRA    20             // 148 - 128
#define GRID_MAIN 148

typedef unsigned long long ull;

__device__ __forceinline__ float ex2f(float q) {
    float r; asm("ex2.approx.ftz.f32 %0, %1;" : "=f"(r) : "f"(q)); return r;
}

// Scratch (static __device__ globals: allocation-free per harness rules)
__device__ float4 g_P[OUTF * INF];        // {inv, ty, wzC, nwz}
__device__ float  g_Xx[INF * BATCH];      // x transposed [i][b]
__device__ float  g_wav[BATCH * OUTF];    // wavelet sums, stages 0..27
__device__ float  g_part[BATCH * OUTF];   // wavelet partials, stages 28..31
__device__ __nv_bfloat16 g_Ah[BATCH * INF], g_Al[BATCH * INF];   // silu(x) hi/lo
__device__ __nv_bfloat16 g_Wh[OUTF * INF], g_Wl[OUTF * INF];     // base_w hi/lo

#define PBLOCKS 1024
#define TBLOCKS 512

// ---------------------------------------------------------------------------
__global__ void prep_all(const float* __restrict__ x,
                         const float* __restrict__ bw, const float* __restrict__ ww,
                         const float* __restrict__ sc, const float* __restrict__ tr) {
    if (blockIdx.x < PBLOCKS) {
        int idx = blockIdx.x * 256 + threadIdx.x;
        const float K = 0.84936056542f;          // sqrt(1/(2ln2))
        float inv = K * __frcp_rn(sc[idx]);
        float wz  = ww[idx];
        float4 p;
        p.x = inv;
        p.y = -tr[idx] * inv;
        p.z = -1.38629436112f * wz;              // -2ln2 * wz
        p.w = -wz;
        g_P[idx] = p;
        float wv = bw[idx];
        __nv_bfloat16 h = __float2bfloat16(wv);
        g_Wh[idx] = h;
        g_Wl[idx] = __float2bfloat16(wv - __bfloat162float(h));
    } else {
        __shared__ float tX[32][33];
        int bt = blockIdx.x - PBLOCKS;
        int i0 = (bt & 15) * 32;
        int b0 = (bt >> 4) * 32;
        int tc = threadIdx.x & 31;
        int tr_ = threadIdx.x >> 5;
        #pragma unroll
        for (int j = 0; j < 4; ++j) {
            int r = tr_ + 8 * j;
            float v = x[(size_t)(b0 + r) * INF + i0 + tc];
            float e = __expf(-v);
            float s = v / (1.0f + e);            // silu
            tX[r][tc] = v;
            __nv_bfloat16 h = __float2bfloat16(s);
            size_t ai = (size_t)(b0 + r) * INF + i0 + tc;
            g_Ah[ai] = h;
            g_Al[ai] = __float2bfloat16(s - __bfloat162float(h));
        }
        __syncthreads();
        #pragma unroll
        for (int j = 0; j < 4; ++j) {
            int r = tr_ + 8 * j;
            g_Xx[(size_t)(i0 + r) * BATCH + b0 + tc] = tX[tc][r];
        }
    }
}

// ---------------------------------------------------------------------------
// Wavelet kernel (validated R14 version, unchanged)
// ---------------------------------------------------------------------------
__shared__ float4 sP[2][KT][OT];        // 32 KB (swizzled cols)
__shared__ float4 sX[2][KT][BT / 4];    //  8 KB

__device__ __forceinline__ void load_stage(int s, int buf, int b0, int o0, int tid) {
    const int k0 = s * KT;
    #pragma unroll
    for (int j = 0; j < 4; ++j) {
        int idx = j * 256 + tid;
        int k   = idx & 15;
        int o   = idx >> 4;
        const float4* src = &g_P[(size_t)(o0 + o) * INF + (k0 + k)];
        uint32_t dst = (uint32_t)__cvta_generic_to_shared(&sP[buf][k][o ^ (k & 7)]);
        asm volatile("cp.async.cg.shared.global [%0], [%1], 16;\n" :: "r"(dst), "l"(src));
    }
    {
        int k  = tid >> 4;
        int b4 = tid & 15;
        const float* srcx = &g_Xx[(size_t)(k0 + k) * BATCH + b0 + b4 * 4];
        uint32_t dstx = (uint32_t)__cvta_generic_to_shared(&sX[buf][k][b4]);
        asm volatile("cp.async.cg.shared.global [%0], [%1], 16;\n" :: "r"(dstx), "l"(srcx));
    }
    asm volatile("cp.async.commit_group;\n" ::);
}

__device__ __forceinline__ void run_tile(int b0, int o0, int s_begin, int s_end,
                                         float* __restrict__ dst) {
    const int tid = threadIdx.x;
    const int tb  = tid & 15;
    const int to  = tid >> 4;

    float acc[4][4];
    #pragma unroll
    for (int i = 0; i < 4; ++i)
        #pragma unroll
        for (int j = 0; j < 4; ++j) acc[i][j] = 0.0f;

    load_stage(s_begin, 0, b0, o0, tid);
    load_stage(s_begin + 1, 1, b0, o0, tid);

    #pragma unroll 1
    for (int s = s_begin; s < s_end; ++s) {
        asm volatile("cp.async.wait_group 1;\n" ::);
        __syncthreads();
        const int buf = (s - s_begin) & 1;

        #pragma unroll 8
        for (int k = 0; k < KT; ++k) {
            float4 xa = sX[buf][k][tb];
            float xv[4] = {xa.x, xa.y, xa.z, xa.w};
            #pragma unroll
            for (int oo = 0; oo < 4; ++oo) {
                float4 p = sP[buf][k][(4 * to + oo) ^ (k & 7)];
                #pragma unroll
                for (int bb = 0; bb < 4; ++bb) {
                    float w  = fmaf(xv[bb], p.x, p.y);
                    float qn = w * (-w);
                    float e  = ex2f(qn);
                    float mp = fmaf(qn, p.z, p.w);
                    acc[bb][oo] = fmaf(mp, e, acc[bb][oo]);
                }
            }
        }
        __syncthreads();
        if (s + 2 < s_end) load_stage(s + 2, buf, b0, o0, tid);
        else               asm volatile("cp.async.commit_group;\n" ::);
    }

    #pragma unroll
    for (int bb = 0; bb < 4; ++bb) {
        int b = b0 + 4 * tb + bb;
        float4 r;
        r.x = acc[bb][0]; r.y = acc[bb][1]; r.z = acc[bb][2]; r.w = acc[bb][3];
        *reinterpret_cast<float4*>(dst + (size_t)b * OUTF + o0 + 4 * to) = r;
    }
}

__global__ void __launch_bounds__(256)
wkan_main() {
    const int c = blockIdx.x;
    if (c < NMAIN) {
        int b0 = (c & 15) * BT;
        int o0 = (c >> 4) * OT;
        run_tile(b0, o0, 0, MAIN_S, g_wav);
    } else {
        for (int t = c - NMAIN; t < NTILES; t += NEXTRA) {
            int b0 = (t & 15) * BT;
            int o0 = (t >> 4) * OT;
            run_tile(b0, o0, MAIN_S, NSTAGES, g_part);
            __syncthreads();
        }
    }
}

// ---------------------------------------------------------------------------
// Base GEMM: HMMA m16n8k16 bf16 with smem-staged, swizzled tiles + ldmatrix.
// CTA tile 64b x 64o, K-chunks of 64. 8 warps: (wb 0..3 = 16 b-rows, wo 0..1 =
// 32 o-cols). Split precision hh + hl + lh. Epilogue fuses bias+g_wav+g_part.
// ---------------------------------------------------------------------------
__device__ __forceinline__ void mma_bf16(float* c, const uint32_t* a,
                                         uint32_t b0, uint32_t b1) {
    asm volatile(
        "mma.sync.aligned.m16n8k16.row.col.f32.bf16.bf16.f32 "
        "{%0,%1,%2,%3}, {%4,%5,%6,%7}, {%8,%9}, {%0,%1,%2,%3};"
        : "+f"(c[0]), "+f"(c[1]), "+f"(c[2]), "+f"(c[3])
        : "r"(a[0]), "r"(a[1]), "r"(a[2]), "r"(a[3]), "r"(b0), "r"(b1));
}
__device__ __forceinline__ void ldsm_x4(uint32_t* r, uint32_t addr) {
    asm volatile("ldmatrix.sync.aligned.m8n8.x4.shared.b16 {%0,%1,%2,%3}, [%4];"
                 : "=r"(r[0]), "=r"(r[1]), "=r"(r[2]), "=r"(r[3]) : "r"(addr));
}

__global__ void __launch_bounds__(256)
gemm_hmma(const float* __restrict__ bias, float* __restrict__ out) {
    // k-chunk = 64 bf16 = 128B rows; 8 x 16B chunks, XOR swizzle (cc ^ (r&7))
    __shared__ __align__(16) __nv_bfloat16 sAh[64 * 64];   // 8 KB
    __shared__ __align__(16) __nv_bfloat16 sAl[64 * 64];   // 8 KB
    __shared__ __align__(16) __nv_bfloat16 sWh[64 * 64];   // 8 KB
    __shared__ __align__(16) __nv_bfloat16 sWl[64 * 64];   // 8 KB

    const int tid  = threadIdx.x;
    const int warp = tid >> 5;
    const int lane = tid & 31;
    const int wb   = warp & 3;          // 16 b-rows each
    const int wo   = warp >> 2;         // 32 o-cols each
    const int g    = lane >> 2;
    const int t    = lane & 3;
    const int b0   = blockIdx.x * 64;
    const int o0   = blockIdx.y * 64;

    uint32_t aAh = (uint32_t)__cvta_generic_to_shared(sAh);
    uint32_t aAl = (uint32_t)__cvta_generic_to_shared(sAl);
    uint32_t aWh = (uint32_t)__cvta_generic_to_shared(sWh);
    uint32_t aWl = (uint32_t)__cvta_generic_to_shared(sWl);

    float acc[4][4];                    // [n8-tile j][frag]
    #pragma unroll
    for (int n = 0; n < 4; ++n)
        #pragma unroll
        for (int j = 0; j < 4; ++j) acc[n][j] = 0.0f;

    // ldmatrix lane->address precompute
    // A (x4): lanes 0-15 -> rows m0..15 (k-low 16B), lanes 16-31 -> same rows k-high
    const int a_row   = wb * 16 + (lane & 15);
    const int a_khalf = lane >> 4;
    // B (x4 covers two n8 tiles): group = lane>>3: {j0 klow, j0+1 klow, j0 khigh, j0+1 khigh}
    const int b_sub   = (lane >> 3) & 1;     // which n8 of the pair
    const int b_khalf = lane >> 4;
    const int b_rowin = lane & 7;

    #pragma unroll 1
    for (int c = 0; c < 8; ++c) {
        // ---- stage A/W hi+lo chunks (coalesced 16B cp.async, swizzled STS) ----
        #pragma unroll
        for (int j = 0; j < 2; ++j) {
            int idx = j * 256 + tid;          // 512 chunks: r=row(0..63), cc=chunk(0..7)
            int r = idx >> 3, cc = idx & 7;
            int sw = r * 128 + (cc ^ (r & 7)) * 16;
            const __nv_bfloat16* s1 = &g_Ah[(size_t)(b0 + r) * INF + c * 64 + cc * 8];
            const __nv_bfloat16* s2 = &g_Al[(size_t)(b0 + r) * INF + c * 64 + cc * 8];
            const __nv_bfloat16* s3 = &g_Wh[(size_t)(o0 + r) * INF + c * 64 + cc * 8];
            const __nv_bfloat16* s4 = &g_Wl[(size_t)(o0 + r) * INF + c * 64 + cc * 8];
            asm volatile("cp.async.cg.shared.global [%0], [%1], 16;\n" :: "r"(aAh + sw), "l"(s1));
            asm volatile("cp.async.cg.shared.global [%0], [%1], 16;\n" :: "r"(aAl + sw), "l"(s2));
            asm volatile("cp.async.cg.shared.global [%0], [%1], 16;\n" :: "r"(aWh + sw), "l"(s3));
            asm volatile("cp.async.cg.shared.global [%0], [%1], 16;\n" :: "r"(aWl + sw), "l"(s4));
        }
        asm volatile("cp.async.commit_group;\n" ::);
        asm volatile("cp.async.wait_group 0;\n" ::);
        __syncthreads();

        #pragma unroll
        for (int kk = 0; kk < 4; ++kk) {    // 4 x k16 within the 64-chunk
            int a_off = a_row * 128 + ((kk * 2 + a_khalf) ^ (a_row & 7)) * 16;
            uint32_t ah[4], al[4];
            ldsm_x4(ah, aAh + a_off);
            ldsm_x4(al, aAl + a_off);
            #pragma unroll
            for (int jj = 0; jj < 2; ++jj) {    // n8-tile pairs: j = 2jj, 2jj+1
                int o_row = wo * 32 + (2 * jj + b_sub) * 8 + b_rowin;
                int w_off = o_row * 128 + ((kk * 2 + b_khalf) ^ (o_row & 7)) * 16;
                uint32_t bh[4], bl[4];
                ldsm_x4(bh, aWh + w_off);   // {j klow, j1 klow, j khigh, j1 khigh}
                ldsm_x4(bl, aWl + w_off);
                mma_bf16(acc[2 * jj],     ah, bh[0], bh[2]);   // hh
                mma_bf16(acc[2 * jj],     ah, bl[0], bl[2]);   // hl
                mma_bf16(acc[2 * jj],     al, bh[0], bh[2]);   // lh
                mma_bf16(acc[2 * jj + 1], ah, bh[1], bh[3]);
                mma_bf16(acc[2 * jj + 1], ah, bl[1], bl[3]);
                mma_bf16(acc[2 * jj + 1], al, bh[1], bh[3]);
            }
        }
        __syncthreads();
    }

    // ---- epilogue: D frag (g=row, 2t..2t+1 = cols; halves at row+8) ----
    #pragma unroll
    for (int n = 0; n < 4; ++n) {
        int oc = o0 + wo * 32 + n * 8 + 2 * t;
        float2 bv = *reinterpret_cast<const float2*>(&bias[oc]);
        #pragma unroll
        for (int half = 0; half < 2; ++half) {
            int b = b0 + wb * 16 + g + half * 8;
            size_t off = (size_t)b * OUTF + oc;
            float2 wv = *reinterpret_cast<const float2*>(&g_wav[off]);
            float2 pv = *reinterpret_cast<const float2*>(&g_part[off]);
            float2 r;
            r.x = acc[n][2 * half]     + bv.x + wv.x + pv.x;
            r.y = acc[n][2 * half + 1] + bv.y + wv.y + pv.y;
            *reinterpret_cast<float2*>(&out[off]) = r;
        }
    }
}

// ---------------------------------------------------------------------------
extern "C" void kernel_launch(void* const* d_in, const int* in_sizes, int n_in,
                              void* d_out, int out_size) {
    (void)in_sizes; (void)n_in; (void)out_size;
    const float* x    = (const float*)d_in[0];
    const float* bw   = (const float*)d_in[1];
    const float* ww   = (const float*)d_in[2];
    const float* sc   = (const float*)d_in[3];
    const float* tr   = (const float*)d_in[4];
    const float* bias = (const float*)d_in[5];
    float* out = (float*)d_out;

    prep_all<<<PBLOCKS + TBLOCKS, 256>>>(x, bw, ww, sc, tr);
    wkan_main<<<GRID_MAIN, 256>>>();
    gemm_hmma<<<dim3(16, 8), 256>>>(bias, out);
}

// round 16
// speedup vs baseline: 1.4618x; 1.0224x over previous
#include <cuda_runtime.h>
#include <cuda_bf16.h>
#include <cstdint>

#define BATCH 1024
#define INF   512
#define OUTF  512
#define BT    64
#define OT    64
#define KT    16
#define NSTAGES   (INF / KT)     // 32
#define MAIN_S    29             // stages done by main wavelet CTAs
#define NTILES    128            // 16 b-tiles x 8 o-tiles
#define NMAIN     128
#define NEXTRA    20             // 148 - 128
#define NWAVE     148            // wavelet CTAs
#define NGEMM     128            // gemm CTAs
#define GRID_FUSED (NWAVE + NGEMM)

typedef unsigned long long ull;

__device__ __forceinline__ float ex2f(float q) {
    float r; asm("ex2.approx.ftz.f32 %0, %1;" : "=f"(r) : "f"(q)); return r;
}

// Scratch (static __device__ globals: allocation-free per harness rules)
__device__ float4 g_P[OUTF * INF];        // {inv, ty, wzC, nwz}
__device__ float  g_Xx[INF * BATCH];      // x transposed [i][b]
__device__ float  g_wav[BATCH * OUTF];    // wavelet sums, stages 0..MAIN_S-1
__device__ float  g_part[BATCH * OUTF];   // wavelet partials, stages MAIN_S..31
__device__ __nv_bfloat16 g_Ah[BATCH * INF], g_Al[BATCH * INF];   // silu(x) hi/lo
__device__ __nv_bfloat16 g_Wh[OUTF * INF], g_Wl[OUTF * INF];     // base_w hi/lo
__device__ unsigned int  g_done;          // wavelet-CTA completion counter

#define PBLOCKS 1024
#define TBLOCKS 512

// ---------------------------------------------------------------------------
__global__ void prep_all(const float* __restrict__ x,
                         const float* __restrict__ bw, const float* __restrict__ ww,
                         const float* __restrict__ sc, const float* __restrict__ tr) {
    if (blockIdx.x == 0 && threadIdx.x == 0) g_done = 0;   // reset per replay
    if (blockIdx.x < PBLOCKS) {
        int idx = blockIdx.x * 256 + threadIdx.x;
        const float K = 0.84936056542f;          // sqrt(1/(2ln2))
        float inv = K * __frcp_rn(sc[idx]);
        float wz  = ww[idx];
        float4 p;
        p.x = inv;
        p.y = -tr[idx] * inv;
        p.z = -1.38629436112f * wz;              // -2ln2 * wz
        p.w = -wz;
        g_P[idx] = p;
        float wv = bw[idx];
        __nv_bfloat16 h = __float2bfloat16(wv);
        g_Wh[idx] = h;
        g_Wl[idx] = __float2bfloat16(wv - __bfloat162float(h));
    } else {
        __shared__ float tX[32][33];
        int bt = blockIdx.x - PBLOCKS;
        int i0 = (bt & 15) * 32;
        int b0 = (bt >> 4) * 32;
        int tc = threadIdx.x & 31;
        int tr_ = threadIdx.x >> 5;
        #pragma unroll
        for (int j = 0; j < 4; ++j) {
            int r = tr_ + 8 * j;
            float v = x[(size_t)(b0 + r) * INF + i0 + tc];
            float e = __expf(-v);
            float s = v / (1.0f + e);            // silu
            tX[r][tc] = v;
            __nv_bfloat16 h = __float2bfloat16(s);
            size_t ai = (size_t)(b0 + r) * INF + i0 + tc;
            g_Ah[ai] = h;
            g_Al[ai] = __float2bfloat16(s - __bfloat162float(h));
        }
        __syncthreads();
        #pragma unroll
        for (int j = 0; j < 4; ++j) {
            int r = tr_ + 8 * j;
            g_Xx[(size_t)(i0 + r) * BATCH + b0 + tc] = tX[tc][r];
        }
    }
}

// ---------------------------------------------------------------------------
// Shared tiles: wavelet uses sP+sX (40 KB). GEMM CTAs alias sP (32 KB) as
// their four bf16 tiles — different CTAs, no conflict.
// ---------------------------------------------------------------------------
__shared__ float4 sP[2][KT][OT];        // 32 KB (swizzled cols)
__shared__ float4 sX[2][KT][BT / 4];    //  8 KB

__device__ __forceinline__ void load_stage(int s, int buf, int b0, int o0, int tid) {
    const int k0 = s * KT;
    #pragma unroll
    for (int j = 0; j < 4; ++j) {
        int idx = j * 256 + tid;
        int k   = idx & 15;
        int o   = idx >> 4;
        const float4* src = &g_P[(size_t)(o0 + o) * INF + (k0 + k)];
        uint32_t dst = (uint32_t)__cvta_generic_to_shared(&sP[buf][k][o ^ (k & 7)]);
        asm volatile("cp.async.cg.shared.global [%0], [%1], 16;\n" :: "r"(dst), "l"(src));
    }
    {
        int k  = tid >> 4;
        int b4 = tid & 15;
        const float* srcx = &g_Xx[(size_t)(k0 + k) * BATCH + b0 + b4 * 4];
        uint32_t dstx = (uint32_t)__cvta_generic_to_shared(&sX[buf][k][b4]);
        asm volatile("cp.async.cg.shared.global [%0], [%1], 16;\n" :: "r"(dstx), "l"(srcx));
    }
    asm volatile("cp.async.commit_group;\n" ::);
}

__device__ __forceinline__ void run_tile(int b0, int o0, int s_begin, int s_end,
                                         float* __restrict__ dst) {
    const int tid = threadIdx.x;
    const int tb  = tid & 15;
    const int to  = tid >> 4;

    float acc[4][4];
    #pragma unroll
    for (int i = 0; i < 4; ++i)
        #pragma unroll
        for (int j = 0; j < 4; ++j) acc[i][j] = 0.0f;

    load_stage(s_begin, 0, b0, o0, tid);
    load_stage(s_begin + 1, 1, b0, o0, tid);

    #pragma unroll 1
    for (int s = s_begin; s < s_end; ++s) {
        asm volatile("cp.async.wait_group 1;\n" ::);
        __syncthreads();
        const int buf = (s - s_begin) & 1;

        #pragma unroll 8
        for (int k = 0; k < KT; ++k) {
            float4 xa = sX[buf][k][tb];
            float xv[4] = {xa.x, xa.y, xa.z, xa.w};
            #pragma unroll
            for (int oo = 0; oo < 4; ++oo) {
                float4 p = sP[buf][k][(4 * to + oo) ^ (k & 7)];
                #pragma unroll
                for (int bb = 0; bb < 4; ++bb) {
                    float w  = fmaf(xv[bb], p.x, p.y);
                    float qn = w * (-w);
                    float e  = ex2f(qn);
                    float mp = fmaf(qn, p.z, p.w);
                    acc[bb][oo] = fmaf(mp, e, acc[bb][oo]);
                }
            }
        }
        __syncthreads();
        if (s + 2 < s_end) load_stage(s + 2, buf, b0, o0, tid);
        else               asm volatile("cp.async.commit_group;\n" ::);
    }

    #pragma unroll
    for (int bb = 0; bb < 4; ++bb) {
        int b = b0 + 4 * tb + bb;
        float4 r;
        r.x = acc[bb][0]; r.y = acc[bb][1]; r.z = acc[bb][2]; r.w = acc[bb][3];
        *reinterpret_cast<float4*>(dst + (size_t)b * OUTF + o0 + 4 * to) = r;
    }
}

// ---------------------------------------------------------------------------
// HMMA helpers (validated R15 numerics)
// ---------------------------------------------------------------------------
__device__ __forceinline__ void mma_bf16(float* c, const uint32_t* a,
                                         uint32_t b0, uint32_t b1) {
    asm volatile(
        "mma.sync.aligned.m16n8k16.row.col.f32.bf16.bf16.f32 "
        "{%0,%1,%2,%3}, {%4,%5,%6,%7}, {%8,%9}, {%0,%1,%2,%3};"
        : "+f"(c[0]), "+f"(c[1]), "+f"(c[2]), "+f"(c[3])
        : "r"(a[0]), "r"(a[1]), "r"(a[2]), "r"(a[3]), "r"(b0), "r"(b1));
}
__device__ __forceinline__ void ldsm_x4(uint32_t* r, uint32_t addr) {
    asm volatile("ldmatrix.sync.aligned.m8n8.x4.shared.b16 {%0,%1,%2,%3}, [%4];"
                 : "=r"(r[0]), "=r"(r[1]), "=r"(r[2]), "=r"(r[3]) : "r"(addr));
}

// ---------------------------------------------------------------------------
// Fused kernel: CTAs [0,148) wavelet -> g_wav/g_part, release g_done.
// CTAs [148,276) HMMA gemm; spin for g_done==148 before fused epilogue.
// One-way dependency: gemm waits on wavelet, never vice versa -> deadlock-free
// even without co-residency (then it just serializes).
// ---------------------------------------------------------------------------
__global__ void __launch_bounds__(256)
wkan_fused(const float* __restrict__ bias, float* __restrict__ out) {
    const int cid = blockIdx.x;
    const int tid = threadIdx.x;

    if (cid < NWAVE) {
        // ================= wavelet path =================
        if (cid < NMAIN) {
            int b0 = (cid & 15) * BT;
            int o0 = (cid >> 4) * OT;
            run_tile(b0, o0, 0, MAIN_S, g_wav);
        } else {
            for (int t = cid - NMAIN; t < NTILES; t += NEXTRA) {
                int b0 = (t & 15) * BT;
                int o0 = (t >> 4) * OT;
                run_tile(b0, o0, MAIN_S, NSTAGES, g_part);
                __syncthreads();
            }
        }
        __threadfence();            // make g_wav/g_part visible device-wide
        __syncthreads();
        if (tid == 0) atomicAdd(&g_done, 1u);
        return;
    }

    // ================= gemm path =================
    const int c   = cid - NWAVE;
    const int warp = tid >> 5;
    const int lane = tid & 31;
    const int wb   = warp & 3;
    const int wo   = warp >> 2;
    const int g    = lane >> 2;
    const int t    = lane & 3;
    const int b0   = (c & 15) * 64;
    const int o0   = (c >> 4) * 64;

    // alias wavelet's sP (32 KB) as four 8 KB bf16 tiles
    __nv_bfloat16* sAh = reinterpret_cast<__nv_bfloat16*>(sP);
    uint32_t aAh = (uint32_t)__cvta_generic_to_shared(sAh);
    uint32_t aAl = aAh + 8192;
    uint32_t aWh = aAh + 16384;
    uint32_t aWl = aAh + 24576;

    float acc[4][4];
    #pragma unroll
    for (int n = 0; n < 4; ++n)
        #pragma unroll
        for (int j = 0; j < 4; ++j) acc[n][j] = 0.0f;

    const int a_row   = wb * 16 + (lane & 15);
    const int a_khalf = lane >> 4;
    const int b_sub   = (lane >> 3) & 1;
    const int b_khalf = lane >> 4;
    const int b_rowin = lane & 7;

    #pragma unroll 1
    for (int cc8 = 0; cc8 < 8; ++cc8) {
        #pragma unroll
        for (int j = 0; j < 2; ++j) {
            int idx = j * 256 + tid;
            int r = idx >> 3, cc = idx & 7;
            int sw = r * 128 + (cc ^ (r & 7)) * 16;
            const __nv_bfloat16* s1 = &g_Ah[(size_t)(b0 + r) * INF + cc8 * 64 + cc * 8];
            const __nv_bfloat16* s2 = &g_Al[(size_t)(b0 + r) * INF + cc8 * 64 + cc * 8];
            const __nv_bfloat16* s3 = &g_Wh[(size_t)(o0 + r) * INF + cc8 * 64 + cc * 8];
            const __nv_bfloat16* s4 = &g_Wl[(size_t)(o0 + r) * INF + cc8 * 64 + cc * 8];
            asm volatile("cp.async.cg.shared.global [%0], [%1], 16;\n" :: "r"(aAh + sw), "l"(s1));
            asm volatile("cp.async.cg.shared.global [%0], [%1], 16;\n" :: "r"(aAl + sw), "l"(s2));
            asm volatile("cp.async.cg.shared.global [%0], [%1], 16;\n" :: "r"(aWh + sw), "l"(s3));
            asm volatile("cp.async.cg.shared.global [%0], [%1], 16;\n" :: "r"(aWl + sw), "l"(s4));
        }
        asm volatile("cp.async.commit_group;\n" ::);
        asm volatile("cp.async.wait_group 0;\n" ::);
        __syncthreads();

        #pragma unroll
        for (int kk = 0; kk < 4; ++kk) {
            int a_off = a_row * 128 + ((kk * 2 + a_khalf) ^ (a_row & 7)) * 16;
            uint32_t ah[4], al[4];
            ldsm_x4(ah, aAh + a_off);
            ldsm_x4(al, aAl + a_off);
            #pragma unroll
            for (int jj = 0; jj < 2; ++jj) {
                int o_row = wo * 32 + (2 * jj + b_sub) * 8 + b_rowin;
                int w_off = o_row * 128 + ((kk * 2 + b_khalf) ^ (o_row & 7)) * 16;
                uint32_t bh[4], bl[4];
                ldsm_x4(bh, aWh + w_off);
                ldsm_x4(bl, aWl + w_off);
                mma_bf16(acc[2 * jj],     ah, bh[0], bh[2]);   // hh
                mma_bf16(acc[2 * jj],     ah, bl[0], bl[2]);   // hl
                mma_bf16(acc[2 * jj],     al, bh[0], bh[2]);   // lh
                mma_bf16(acc[2 * jj + 1], ah, bh[1], bh[3]);
                mma_bf16(acc[2 * jj + 1], ah, bl[1], bl[3]);
                mma_bf16(acc[2 * jj + 1], al, bh[1], bh[3]);
            }
        }
        __syncthreads();
    }

    // ---- wait for wavelet completion (one-way; deadlock-free) ----
    if (tid == 0) {
        while (*(volatile unsigned int*)&g_done < (unsigned)NWAVE) __nanosleep(200);
    }
    __syncthreads();
    __threadfence();    // acquire-side ordering before reading g_wav/g_part

    // ---- fused epilogue: out = gemm + bias + g_wav + g_part ----
    #pragma unroll
    for (int n = 0; n < 4; ++n) {
        int oc = o0 + wo * 32 + n * 8 + 2 * t;
        float2 bv = *reinterpret_cast<const float2*>(&bias[oc]);
        #pragma unroll
        for (int half = 0; half < 2; ++half) {
            int b = b0 + wb * 16 + g + half * 8;
            size_t off = (size_t)b * OUTF + oc;
            float2 wv = *reinterpret_cast<const float2*>(&g_wav[off]);
            float2 pv = *reinterpret_cast<const float2*>(&g_part[off]);
            float2 r;
            r.x = acc[n][2 * half]     + bv.x + wv.x + pv.x;
            r.y = acc[n][2 * half + 1] + bv.y + wv.y + pv.y;
            *reinterpret_cast<float2*>(&out[off]) = r;
        }
    }
}

// ---------------------------------------------------------------------------
extern "C" void kernel_launch(void* const* d_in, const int* in_sizes, int n_in,
                              void* d_out, int out_size) {
    (void)in_sizes; (void)n_in; (void)out_size;
    const float* x    = (const float*)d_in[0];
    const float* bw   = (const float*)d_in[1];
    const float* ww   = (const float*)d_in[2];
    const float* sc   = (const float*)d_in[3];
    const float* tr   = (const float*)d_in[4];
    const float* bias = (const float*)d_in[5];
    float* out = (float*)d_out;

    prep_all<<<PBLOCKS + TBLOCKS, 256>>>(x, bw, ww, sc, tr);
    wkan_fused<<<GRID_FUSED, 256>>>(bias, out);
}